// round 1
// baseline (speedup 1.0000x reference)
#include <cuda_runtime.h>
#include <math.h>

#define HH 256
#define BM 64
#define BN 32
#define KT 32

// tree constants: B=8, D=7
static const int OFFS[7] = {0, 1, 9, 73, 585, 4681, 37449};
static const int SZS[7]  = {1, 8, 64, 512, 4096, 32768, 262144};

// scratch (device globals; no runtime allocation allowed)
__device__ float g_enc[299593 * 256];   // per-node encodings (same layout as ctx)
__device__ float g_hl0[262144 * 256];   // left-chain h ping (leaf-sized)
__device__ float g_hr0[262144 * 256];   // right-chain h ping
__device__ float g_hl1[32768 * 256];    // pong (only needed when T>1 -> n<=32768)
__device__ float g_hr1[32768 * 256];
__device__ float g_cl[32768 * 256];     // cell states (in-place safe)
__device__ float g_cr[32768 * 256];

__device__ __forceinline__ float sigf(float x) { return 1.0f / (1.0f + expf(-x)); }

// One LSTM time step for a batch of n sequences, fused GEMM + gates.
// x row for batch element i = X[(x_base + i*x_stride) * 256 ...]
// Tile: 64 rows x 32 h-cols x 4 gates. Thread: 8 rows x 1 col x 4 gates.
__global__ __launch_bounds__(256) void lstm_step_kernel(
    const float* __restrict__ X, int x_base, int x_stride,
    const float* __restrict__ Hin, const float* __restrict__ Cin,   // null on first step
    const float* __restrict__ Wih, const float* __restrict__ Whh,   // [1024,256] row-major
    const float* __restrict__ bih, const float* __restrict__ bhh,   // [1024]
    float* __restrict__ Hout, float* __restrict__ Cout,             // Cout null on last step
    int n)
{
    __shared__ float xs[BM][KT + 4];        // x or h tile (broadcast reads)
    __shared__ float ws[4][KT][BN + 1];     // weights: [gate][k][col] conflict-free

    const int tid  = threadIdx.x;
    const int col  = tid & 31;
    const int rg   = tid >> 5;              // 0..7 (8 warps)
    const int row0 = blockIdx.x * BM;
    const int cb   = blockIdx.y * BN;       // h-col base (blockIdx.y in 0..7)

    float acc[8][4];
#pragma unroll
    for (int r = 0; r < 8; r++)
#pragma unroll
        for (int g = 0; g < 4; g++) acc[r][g] = 0.f;

    const int npass = Hin ? 2 : 1;
    for (int pass = 0; pass < npass; pass++) {
        const float* __restrict__ W = pass ? Whh : Wih;
        for (int kt = 0; kt < HH; kt += KT) {
            // load 64x32 x/h tile (float4)
#pragma unroll
            for (int l = tid; l < BM * (KT / 4); l += 256) {
                int r = l >> 3, kq = l & 7;
                int grow = row0 + r;
                float4 v = make_float4(0.f, 0.f, 0.f, 0.f);
                if (grow < n) {
                    if (pass == 0)
                        v = *(const float4*)(X + (size_t)(x_base + grow * x_stride) * HH + kt + kq * 4);
                    else
                        v = *(const float4*)(Hin + (size_t)grow * HH + kt + kq * 4);
                }
                *(float4*)&xs[r][kq * 4] = v;
            }
            // load 4 gates x 32 cols x 32 k weight tile
#pragma unroll
            for (int l = tid; l < 4 * BN * (KT / 4); l += 256) {
                int kq = l & 7;
                int j  = (l >> 3) & 31;
                int g  = l >> 8;
                float4 v = *(const float4*)(W + (size_t)(g * HH + cb + j) * HH + kt + kq * 4);
                ws[g][kq * 4 + 0][j] = v.x;
                ws[g][kq * 4 + 1][j] = v.y;
                ws[g][kq * 4 + 2][j] = v.z;
                ws[g][kq * 4 + 3][j] = v.w;
            }
            __syncthreads();
#pragma unroll
            for (int kk = 0; kk < KT; kk++) {
                float xr[8], wv[4];
#pragma unroll
                for (int r = 0; r < 8; r++) xr[r] = xs[rg * 8 + r][kk];   // warp-uniform row -> broadcast
#pragma unroll
                for (int g = 0; g < 4; g++) wv[g] = ws[g][kk][col];       // consecutive -> conflict-free
#pragma unroll
                for (int r = 0; r < 8; r++)
#pragma unroll
                    for (int g = 0; g < 4; g++)
                        acc[r][g] = fmaf(xr[r], wv[g], acc[r][g]);
            }
            __syncthreads();
        }
    }

    // fused pointwise: torch gate order i, f, g, o
    const int jc = cb + col;
    float bsum[4];
#pragma unroll
    for (int g = 0; g < 4; g++) bsum[g] = bih[g * HH + jc] + bhh[g * HH + jc];

#pragma unroll
    for (int r = 0; r < 8; r++) {
        int grow = row0 + rg * 8 + r;
        if (grow < n) {
            float iv = sigf(acc[r][0] + bsum[0]);
            float fv = sigf(acc[r][1] + bsum[1]);
            float gv = tanhf(acc[r][2] + bsum[2]);
            float ov = sigf(acc[r][3] + bsum[3]);
            float cp = Cin ? Cin[(size_t)grow * HH + jc] : 0.f;
            float cn = fv * cp + iv * gv;
            float hn = ov * tanhf(cn);
            Hout[(size_t)grow * HH + jc] = hn;
            if (Cout) Cout[(size_t)grow * HH + jc] = cn;
        }
    }
}

// enc = tanh([el, er] @ Wenc^T + benc); Wenc [256, 512]
__global__ __launch_bounds__(256) void enc_kernel(
    const float* __restrict__ EL, const float* __restrict__ ER,
    const float* __restrict__ Wenc, const float* __restrict__ benc,
    float* __restrict__ out, int n)
{
    __shared__ float xs[BM][KT + 4];
    __shared__ float ws[KT][BN + 1];

    const int tid  = threadIdx.x;
    const int col  = tid & 31;
    const int rg   = tid >> 5;
    const int row0 = blockIdx.x * BM;
    const int cb   = blockIdx.y * BN;

    float acc[8];
#pragma unroll
    for (int r = 0; r < 8; r++) acc[r] = 0.f;

    for (int pass = 0; pass < 2; pass++) {
        const float* __restrict__ src = pass ? ER : EL;
        for (int kt = 0; kt < HH; kt += KT) {
#pragma unroll
            for (int l = tid; l < BM * (KT / 4); l += 256) {
                int r = l >> 3, kq = l & 7;
                int grow = row0 + r;
                float4 v = make_float4(0.f, 0.f, 0.f, 0.f);
                if (grow < n) v = *(const float4*)(src + (size_t)grow * HH + kt + kq * 4);
                *(float4*)&xs[r][kq * 4] = v;
            }
            {
                int kq = tid & 7, j = tid >> 3;   // 32 cols x 8 quads = 256 threads
                float4 v = *(const float4*)(Wenc + (size_t)(cb + j) * (2 * HH) + pass * HH + kt + kq * 4);
                ws[kq * 4 + 0][j] = v.x;
                ws[kq * 4 + 1][j] = v.y;
                ws[kq * 4 + 2][j] = v.z;
                ws[kq * 4 + 3][j] = v.w;
            }
            __syncthreads();
#pragma unroll
            for (int kk = 0; kk < KT; kk++) {
                float w = ws[kk][col];
#pragma unroll
                for (int r = 0; r < 8; r++)
                    acc[r] = fmaf(xs[rg * 8 + r][kk], w, acc[r]);
            }
            __syncthreads();
        }
    }
    int jc = cb + col;
    float b = benc[jc];
#pragma unroll
    for (int r = 0; r < 8; r++) {
        int grow = row0 + rg * 8 + r;
        if (grow < n) out[(size_t)grow * HH + jc] = tanhf(acc[r] + b);
    }
}

__global__ void copy_out_kernel(float* __restrict__ out) {
    out[threadIdx.x] = g_enc[threadIdx.x];
}

extern "C" void kernel_launch(void* const* d_in, const int* in_sizes, int n_in,
                              void* d_out, int out_size)
{
    const float* node_init = (const float*)d_in[0];
    const float* Wih_l = (const float*)d_in[1];
    const float* Whh_l = (const float*)d_in[2];
    const float* bih_l = (const float*)d_in[3];
    const float* bhh_l = (const float*)d_in[4];
    const float* Wih_r = (const float*)d_in[5];
    const float* Whh_r = (const float*)d_in[6];
    const float* bih_r = (const float*)d_in[7];
    const float* bhh_r = (const float*)d_in[8];
    const float* Wenc  = (const float*)d_in[9];
    const float* benc  = (const float*)d_in[10];

    float *enc, *hl0, *hr0, *hl1, *hr1, *cl, *cr;
    cudaGetSymbolAddress((void**)&enc, g_enc);
    cudaGetSymbolAddress((void**)&hl0, g_hl0);
    cudaGetSymbolAddress((void**)&hr0, g_hr0);
    cudaGetSymbolAddress((void**)&hl1, g_hl1);
    cudaGetSymbolAddress((void**)&hr1, g_hr1);
    cudaGetSymbolAddress((void**)&cl, g_cl);
    cudaGetSymbolAddress((void**)&cr, g_cr);

    for (int d = 6; d >= 0; d--) {
        int off = OFFS[d], n = SZS[d];
        dim3 grid((n + BM - 1) / BM, 8);
        if (d == 6) {
            // leaf: single step, zero initial state; final h always lands in *0 buffer
            lstm_step_kernel<<<grid, 256>>>(node_init, off, 1, nullptr, nullptr,
                                            Wih_l, Whh_l, bih_l, bhh_l, hl0, nullptr, n);
            lstm_step_kernel<<<grid, 256>>>(node_init, off, 1, nullptr, nullptr,
                                            Wih_r, Whh_r, bih_r, bhh_r, hr0, nullptr, n);
        } else {
            int coff = OFFS[d + 1];
            // left chain: child3, child2, child1, child0, own
            for (int t = 0; t < 5; t++) {
                const float* X; int xb, xst;
                if (t < 4) { X = enc; xb = coff + (3 - t); xst = 8; }
                else       { X = node_init; xb = off; xst = 1; }
                const float* Hi = (t == 0) ? nullptr : ((t & 1) ? hl0 : hl1);
                float* Ho = (t & 1) ? hl1 : hl0;              // T=5 -> last step writes hl0
                const float* Ci = (t == 0) ? nullptr : cl;
                float* Co = (t == 4) ? nullptr : cl;
                lstm_step_kernel<<<grid, 256>>>(X, xb, xst, Hi, Ci,
                                                Wih_l, Whh_l, bih_l, bhh_l, Ho, Co, n);
            }
            // right chain: own, child4, child5, child6, child7
            for (int t = 0; t < 5; t++) {
                const float* X; int xb, xst;
                if (t == 0) { X = node_init; xb = off; xst = 1; }
                else        { X = enc; xb = coff + (3 + t); xst = 8; }
                const float* Hi = (t == 0) ? nullptr : ((t & 1) ? hr0 : hr1);
                float* Ho = (t & 1) ? hr1 : hr0;
                const float* Ci = (t == 0) ? nullptr : cr;
                float* Co = (t == 4) ? nullptr : cr;
                lstm_step_kernel<<<grid, 256>>>(X, xb, xst, Hi, Ci,
                                                Wih_r, Whh_r, bih_r, bhh_r, Ho, Co, n);
            }
        }
        enc_kernel<<<grid, 256>>>(hl0, hr0, Wenc, benc, enc + (size_t)off * HH, n);
    }
    copy_out_kernel<<<1, 256>>>((float*)d_out);
}